// round 1
// baseline (speedup 1.0000x reference)
#include <cuda_runtime.h>

// TSK fuzzy system: out[n] = sum_r fg_bar[n,r] * (x[n]·W[r] + b[r])
// fg_bar separable-normalized: mg_norm[n,m,j] = mg/sum_j mg,
// fg_bar[n,r] = prod_m mg_norm[n,m,digit_m(r)], digits MSB-first (j0 most significant).
// out[n] = x[n]·A[n] + c[n],  A[n] = sum_r fg_bar W[r],  c[n] = sum_r fg_bar b[r].

#define NSAMP 1024
#define MDIM 8
#define NMF4 4
#define RRULES 65536
#define GY 32      // rule-chunk groups (grid.y); each CTA covers 8 chunks of 256 rules
#define STILES 32  // sample tiles of 32 (grid.x)

__device__ float g_mg[NSAMP * 32];            // normalized memberships [n][m][j]
__device__ float g_part[GY * NSAMP * 12];     // partials [gy][n][12] (9 used: A0..A7, c)

// ---------------- kernel 1: normalized memberships ----------------
__global__ void mg_kernel(const float* __restrict__ x,
                          const float* __restrict__ center,
                          const float* __restrict__ sigma) {
    int n = blockIdx.x * blockDim.x + threadIdx.x;
    if (n >= NSAMP) return;
#pragma unroll
    for (int m = 0; m < MDIM; m++) {
        float xv = x[n * MDIM + m];
        float e[NMF4];
        float s = 0.f;
#pragma unroll
        for (int j = 0; j < NMF4; j++) {
            float d = xv - center[m * NMF4 + j];
            float sg = sigma[m * NMF4 + j];
            e[j] = expf(-d * d * 0.5f * sg * sg);
            s += e[j];
        }
        float inv = 1.0f / s;
#pragma unroll
        for (int j = 0; j < NMF4; j++)
            g_mg[n * 32 + m * 4 + j] = e[j] * inv;
    }
}

// ---------------- packed f32x2 helpers (Blackwell) ----------------
__device__ __forceinline__ unsigned long long pack2(float f) {
    unsigned long long r;
    asm("mov.b64 %0, {%1, %1};" : "=l"(r) : "f"(f));
    return r;
}
__device__ __forceinline__ void fma2(unsigned long long& d,
                                     unsigned long long a,
                                     unsigned long long b) {
    asm("fma.rn.f32x2 %0, %1, %2, %0;" : "+l"(d) : "l"(a), "l"(b));
}

// ---------------- kernel 2: rule accumulation ----------------
// blockDim 256 = 8 warps x 32 lanes. lane = sample within tile; warp = rule chunk.
// Each warp: 256 contiguous rules (top digits j0..j3 fixed -> one prefix product).
__global__ __launch_bounds__(256) void rules_kernel(const float* __restrict__ W,
                                                    const float* __restrict__ b) {
    __shared__ float s_part[8][32][12];

    int lane = threadIdx.x & 31;
    int w = threadIdx.x >> 5;
    int n = blockIdx.x * 32 + lane;
    int chunk = blockIdx.y * 8 + w;  // 0..255
    int rbase = chunk << 8;

    const float* mg = g_mg + n * 32;
    float prefix = mg[0 + ((chunk >> 6) & 3)]
                 * mg[4 + ((chunk >> 4) & 3)]
                 * mg[8 + ((chunk >> 2) & 3)]
                 * mg[12 + (chunk & 3)];

    float mg4[4], mg5[4], mg6[4], mg7[4];
#pragma unroll
    for (int j = 0; j < 4; j++) {
        mg4[j] = mg[16 + j];
        mg5[j] = mg[20 + j];
        mg6[j] = mg[24 + j];
        mg7[j] = mg[28 + j];
    }

    unsigned long long a01 = 0ull, a23 = 0ull, a45 = 0ull, a67 = 0ull;
    float ab = 0.f;

#pragma unroll
    for (int j4 = 0; j4 < 4; j4++) {
        float p4 = prefix * mg4[j4];
#pragma unroll
        for (int j5 = 0; j5 < 4; j5++) {
            float p5 = p4 * mg5[j5];
            int rb = rbase + j4 * 64 + j5 * 16;  // 16 rules, contiguous
            const ulonglong2* Wp = reinterpret_cast<const ulonglong2*>(W + (size_t)rb * 8);
            const float4* bp = reinterpret_cast<const float4*>(b + rb);
#pragma unroll
            for (int j6 = 0; j6 < 4; j6++) {
                float p6 = p5 * mg6[j6];
                float4 bv = bp[j6];
                float bb[4] = {bv.x, bv.y, bv.z, bv.w};
#pragma unroll
                for (int j7 = 0; j7 < 4; j7++) {
                    int ri = j6 * 4 + j7;
                    float f = p6 * mg7[j7];
                    unsigned long long f2 = pack2(f);
                    ulonglong2 q0 = Wp[ri * 2];
                    ulonglong2 q1 = Wp[ri * 2 + 1];
                    fma2(a01, f2, q0.x);
                    fma2(a23, f2, q0.y);
                    fma2(a45, f2, q1.x);
                    fma2(a67, f2, q1.y);
                    ab = fmaf(f, bb[j7], ab);
                }
            }
        }
    }

    // spill warp partials to smem
    float2 u01 = *reinterpret_cast<float2*>(&a01);
    float2 u23 = *reinterpret_cast<float2*>(&a23);
    float2 u45 = *reinterpret_cast<float2*>(&a45);
    float2 u67 = *reinterpret_cast<float2*>(&a67);
    s_part[w][lane][0] = u01.x;
    s_part[w][lane][1] = u01.y;
    s_part[w][lane][2] = u23.x;
    s_part[w][lane][3] = u23.y;
    s_part[w][lane][4] = u45.x;
    s_part[w][lane][5] = u45.y;
    s_part[w][lane][6] = u67.x;
    s_part[w][lane][7] = u67.y;
    s_part[w][lane][8] = ab;
    __syncthreads();

    // deterministic 8-warp reduction, write per-(rule-group) partials
    for (int idx = threadIdx.x; idx < 32 * 9; idx += 256) {
        int s = idx / 9;
        int k = idx - s * 9;
        float acc = 0.f;
#pragma unroll
        for (int ww = 0; ww < 8; ww++) acc += s_part[ww][s][k];
        int nn = blockIdx.x * 32 + s;
        g_part[(blockIdx.y * NSAMP + nn) * 12 + k] = acc;
    }
}

// ---------------- kernel 3: finalize ----------------
__global__ void final_kernel(const float* __restrict__ x, float* __restrict__ out) {
    int n = blockIdx.x * blockDim.x + threadIdx.x;
    if (n >= NSAMP) return;
    float A[9];
#pragma unroll
    for (int k = 0; k < 9; k++) A[k] = 0.f;
    for (int gy = 0; gy < GY; gy++) {
        const float* p = g_part + (gy * NSAMP + n) * 12;
#pragma unroll
        for (int k = 0; k < 9; k++) A[k] += p[k];
    }
    float o = A[8];
#pragma unroll
    for (int m = 0; m < MDIM; m++) o = fmaf(x[n * MDIM + m], A[m], o);
    out[n] = o;
}

extern "C" void kernel_launch(void* const* d_in, const int* in_sizes, int n_in,
                              void* d_out, int out_size) {
    const float* x      = (const float*)d_in[0];
    const float* center = (const float*)d_in[1];
    const float* sigma  = (const float*)d_in[2];
    const float* W      = (const float*)d_in[3];
    const float* b      = (const float*)d_in[4];
    float* out = (float*)d_out;

    mg_kernel<<<4, 256>>>(x, center, sigma);
    dim3 grid(STILES, GY);
    rules_kernel<<<grid, 256>>>(W, b);
    final_kernel<<<4, 256>>>(x, out);
}